// round 2
// baseline (speedup 1.0000x reference)
#include <cuda_runtime.h>
#include <cstddef>

// BarrierNet fused kernel: obs[B,10] -> silu(L1:10->128) -> silu(L2:128->64, = W21||W22)
// -> L3 (32->2, 32->1) -> CBF-QP projection -> out[B,2] fp32.
//
// Strategy: fp32x2 packed FMA (sm_103a FFMA2) for layers 1 and 2, weights staged
// transposed in SMEM (broadcast LDS.64 per output-pair), activations in registers.

#define NF   10
#define NH1  128
#define NH2  64          // combined 32 (u-branch) + 32 (alpha-branch)
#define BLOCK 256
#define RPT  4           // rows per thread

__device__ __forceinline__ unsigned long long pk2(float lo, float hi) {
    unsigned long long r;
    asm("mov.b64 %0, {%1, %2};" : "=l"(r) : "f"(lo), "f"(hi));
    return r;
}
__device__ __forceinline__ void upk2(unsigned long long v, float& lo, float& hi) {
    asm("mov.b64 {%0, %1}, %2;" : "=f"(lo), "=f"(hi) : "l"(v));
}
__device__ __forceinline__ unsigned long long ffma2(unsigned long long a,
                                                    unsigned long long b,
                                                    unsigned long long c) {
    unsigned long long d;
    asm("fma.rn.f32x2 %0, %1, %2, %3;" : "=l"(d) : "l"(a), "l"(b), "l"(c));
    return d;
}
__device__ __forceinline__ float silu_f(float v) {
    // v * sigmoid(v) = v / (1 + exp(-v)); fast-math intrinsics (~2 ulp) are far
    // inside the 1e-3 tolerance. Large |v| limits behave correctly (x/inf -> 0).
    return __fdividef(v, 1.0f + __expf(-v));
}

struct __align__(16) SW {
    float W1T[NF][NH1];    // [k][j]  (transposed W1)
    float W2T[NH1][NH2];   // [k][j]  j<32: W21 row j, j>=32: W22 row j-32
    float b1[NH1];
    float b2[NH2];
    float W31[64];         // W31[0][:], W31[1][:]
    float W32[32];
    float b31[2];
    float b32;
};

__global__ __launch_bounds__(BLOCK)
void barriernet_kernel(const float* __restrict__ obs,
                       const float* __restrict__ W1,  const float* __restrict__ b1,
                       const float* __restrict__ W21, const float* __restrict__ b21,
                       const float* __restrict__ W22, const float* __restrict__ b22,
                       const float* __restrict__ W31, const float* __restrict__ b31,
                       const float* __restrict__ W32, const float* __restrict__ b32,
                       float2* __restrict__ out, int n)
{
    __shared__ SW s;
    const int tid = threadIdx.x;

    // ---- stage weights (transposed) into SMEM ----
    for (int i = tid; i < NF * NH1; i += BLOCK) {
        int j = i % NH1, k = i / NH1;
        s.W1T[k][j] = W1[j * NF + k];
    }
    for (int i = tid; i < NH1 * NH2; i += BLOCK) {
        int j = i % NH2, k = i / NH2;
        s.W2T[k][j] = (j < 32) ? W21[j * NH1 + k] : W22[(j - 32) * NH1 + k];
    }
    for (int i = tid; i < NH1; i += BLOCK) s.b1[i] = b1[i];
    for (int i = tid; i < NH2; i += BLOCK) s.b2[i] = (i < 32) ? b21[i] : b22[i - 32];
    for (int i = tid; i < 64;  i += BLOCK) s.W31[i] = W31[i];
    for (int i = tid; i < 32;  i += BLOCK) s.W32[i] = W32[i];
    if (tid == 0) { s.b31[0] = b31[0]; s.b31[1] = b31[1]; s.b32 = b32[0]; }
    __syncthreads();

    const int base = blockIdx.x * (BLOCK * RPT);

    for (int it = 0; it < RPT; ++it) {
        const int r = base + it * BLOCK + tid;
        if (r >= n) break;                       // no syncs below: safe

        const float* o = obs + (size_t)r * NF;
        float ov[NF];
        #pragma unroll
        for (int k = 0; k < NF; ++k) ov[k] = o[k];

        // ---------------- layer 1: 10 -> 128 (f32x2) ----------------
        unsigned long long a1[NH1 / 2];
        #pragma unroll
        for (int t = 0; t < NH1 / 2; ++t)
            a1[t] = *reinterpret_cast<const unsigned long long*>(&s.b1[2 * t]);
        #pragma unroll
        for (int k = 0; k < NF; ++k) {
            const unsigned long long xk = pk2(ov[k], ov[k]);
            #pragma unroll
            for (int t = 0; t < NH1 / 2; ++t) {
                const unsigned long long w =
                    *reinterpret_cast<const unsigned long long*>(&s.W1T[k][2 * t]);
                a1[t] = ffma2(xk, w, a1[t]);
            }
        }
        float x[NH1];
        #pragma unroll
        for (int t = 0; t < NH1 / 2; ++t) {
            float lo, hi; upk2(a1[t], lo, hi);
            x[2 * t] = silu_f(lo); x[2 * t + 1] = silu_f(hi);
        }

        // ---------------- layer 2: 128 -> 64 (f32x2) ----------------
        unsigned long long a2[NH2 / 2];
        #pragma unroll
        for (int t = 0; t < NH2 / 2; ++t)
            a2[t] = *reinterpret_cast<const unsigned long long*>(&s.b2[2 * t]);
        #pragma unroll
        for (int k = 0; k < NH1; ++k) {
            const unsigned long long xk = pk2(x[k], x[k]);
            #pragma unroll
            for (int t = 0; t < NH2 / 2; ++t) {
                const unsigned long long w =
                    *reinterpret_cast<const unsigned long long*>(&s.W2T[k][2 * t]);
                a2[t] = ffma2(xk, w, a2[t]);
            }
        }
        float y[NH2];
        #pragma unroll
        for (int t = 0; t < NH2 / 2; ++t) {
            float lo, hi; upk2(a2[t], lo, hi);
            y[2 * t] = silu_f(lo); y[2 * t + 1] = silu_f(hi);
        }

        // ---------------- layer 3 + epilogue (scalar) ----------------
        float u0 = s.b31[0], u1 = s.b31[1], sv = s.b32;
        #pragma unroll
        for (int i = 0; i < 32; ++i) {
            u0 = fmaf(y[i],      s.W31[i],      u0);
            u1 = fmaf(y[i],      s.W31[32 + i], u1);
            sv = fmaf(y[32 + i], s.W32[i],      sv);
        }
        const float alpha = 4.0f * __fdividef(1.0f, 1.0f + __expf(-sv));

        const float rx = ov[6], ry = ov[7], vx = ov[8], vy = ov[9];
        const float barrier = fmaf(rx, rx, ry * ry) - 0.64f;          // R_SAFE^2
        const float lf  = -2.0f * fmaf(rx, vx, ry * vy);
        const float gx  = -2.0f * rx, gy = -2.0f * ry;
        const float h   = fmaf(alpha, barrier, lf);
        const float gg  = fmaf(gx, gx, gy * gy);
        const float viol = fmaf(gx, u0, gy * u1) - h;
        float lam = 0.0f;
        if (gg > 0.0f)
            lam = __fdividef(fmaxf(viol, 0.0f), fmaxf(gg, 1e-12f));

        out[r] = make_float2(fmaf(-lam, gx, u0), fmaf(-lam, gy, u1));
    }
}

extern "C" void kernel_launch(void* const* d_in, const int* in_sizes, int n_in,
                              void* d_out, int out_size)
{
    const float* obs = (const float*)d_in[0];
    const float* W1  = (const float*)d_in[1];
    const float* b1  = (const float*)d_in[2];
    const float* W21 = (const float*)d_in[3];
    const float* b21 = (const float*)d_in[4];
    const float* W22 = (const float*)d_in[5];
    const float* b22 = (const float*)d_in[6];
    const float* W31 = (const float*)d_in[7];
    const float* b31 = (const float*)d_in[8];
    const float* W32 = (const float*)d_in[9];
    const float* b32 = (const float*)d_in[10];
    float2* out = (float2*)d_out;

    const int n = in_sizes[0] / NF;
    const int rows_per_block = BLOCK * RPT;
    const int grid = (n + rows_per_block - 1) / rows_per_block;

    barriernet_kernel<<<grid, BLOCK>>>(obs, W1, b1, W21, b21, W22, b22,
                                       W31, b31, W32, b32, out, n);
}

// round 3
// speedup vs baseline: 1.3356x; 1.3356x over previous
#include <cuda_runtime.h>
#include <cstddef>

// BarrierNet fused kernel: obs[B,10] -> silu(L1:10->128) -> silu(L2:128->64 = W21||W22)
// -> L3 (32->2, 32->1) -> CBF-QP projection -> out[B,2] fp32.
//
// R2: LDS.128 weight loads (ulonglong2 = 2 packed FFMA2 operands per load) and
// chunked L1->L2 fusion so x[128] is never materialized. Register budget ~125
// -> 2 CTAs/SM (4 warps/SMSP) for latency hiding. fp32x2 packed FMA throughout.

#define NF    10
#define NH1   128
#define NH2   64          // combined 32 (u-branch) + 32 (alpha-branch)
#define BLOCK 256
#define RPT   2           // rows per thread

typedef unsigned long long ull;

__device__ __forceinline__ ull pk2(float lo, float hi) {
    ull r;
    asm("mov.b64 %0, {%1, %2};" : "=l"(r) : "f"(lo), "f"(hi));
    return r;
}
__device__ __forceinline__ void upk2(ull v, float& lo, float& hi) {
    asm("mov.b64 {%0, %1}, %2;" : "=f"(lo), "=f"(hi) : "l"(v));
}
__device__ __forceinline__ ull ffma2(ull a, ull b, ull c) {
    ull d;
    asm("fma.rn.f32x2 %0, %1, %2, %3;" : "=l"(d) : "l"(a), "l"(b), "l"(c));
    return d;
}
__device__ __forceinline__ float silu_f(float v) {
    // v / (1 + exp(-v)); fast-math intrinsics, far inside the 1e-3 tolerance.
    return __fdividef(v, 1.0f + __expf(-v));
}

struct __align__(16) SW {
    float W1T[NF][NH1];    // [k][j]  (transposed W1), rows 512B
    float W2T[NH1][NH2];   // [k][j]  j<32: W21 row j, j>=32: W22 row j-32; rows 256B
    float b1[NH1];
    float b2[NH2];
    float W31[64];         // W31[0][:], W31[1][:]
    float W32[32];
    float b31[2];
    float b32;
};

__global__ __launch_bounds__(BLOCK, 2)
void barriernet_kernel(const float* __restrict__ obs,
                       const float* __restrict__ W1,  const float* __restrict__ b1,
                       const float* __restrict__ W21, const float* __restrict__ b21,
                       const float* __restrict__ W22, const float* __restrict__ b22,
                       const float* __restrict__ W31, const float* __restrict__ b31,
                       const float* __restrict__ W32, const float* __restrict__ b32,
                       float2* __restrict__ out, int n)
{
    __shared__ SW s;
    const int tid = threadIdx.x;

    // ---- stage weights (transposed) into SMEM ----
    for (int i = tid; i < NF * NH1; i += BLOCK) {
        int j = i % NH1, k = i / NH1;
        s.W1T[k][j] = W1[j * NF + k];
    }
    for (int i = tid; i < NH1 * NH2; i += BLOCK) {
        int j = i % NH2, k = i / NH2;
        s.W2T[k][j] = (j < 32) ? W21[j * NH1 + k] : W22[(j - 32) * NH1 + k];
    }
    for (int i = tid; i < NH1; i += BLOCK) s.b1[i] = b1[i];
    for (int i = tid; i < NH2; i += BLOCK) s.b2[i] = (i < 32) ? b21[i] : b22[i - 32];
    for (int i = tid; i < 64;  i += BLOCK) s.W31[i] = W31[i];
    for (int i = tid; i < 32;  i += BLOCK) s.W32[i] = W32[i];
    if (tid == 0) { s.b31[0] = b31[0]; s.b31[1] = b31[1]; s.b32 = b32[0]; }
    __syncthreads();

    const int base = blockIdx.x * (BLOCK * RPT);

    for (int it = 0; it < RPT; ++it) {
        const int r = base + it * BLOCK + tid;
        if (r >= n) break;                       // no syncs below: safe

        // obs row: 40B at 8B alignment -> 5x float2
        float ov[NF];
        {
            const float2* o2 = reinterpret_cast<const float2*>(obs + (size_t)r * NF);
            #pragma unroll
            for (int k = 0; k < NF / 2; ++k) {
                float2 v = o2[k];
                ov[2 * k] = v.x; ov[2 * k + 1] = v.y;
            }
        }

        // Layer-2 accumulators live across the whole row (32 x f32x2 = 64 outputs)
        ull a2[NH2 / 2];
        #pragma unroll
        for (int t = 0; t < NH2 / 2; ++t)
            a2[t] = *reinterpret_cast<const ull*>(&s.b2[2 * t]);

        // ---- fused layer1-chunk -> silu -> layer2-accumulate ----
        #pragma unroll
        for (int c = 0; c < NH1 / 32; ++c) {       // 4 chunks of 32 L1 outputs
            ull acc[16];
            #pragma unroll
            for (int t = 0; t < 16; ++t)
                acc[t] = *reinterpret_cast<const ull*>(&s.b1[c * 32 + 2 * t]);

            #pragma unroll
            for (int k = 0; k < NF; ++k) {
                const ull xk = pk2(ov[k], ov[k]);
                #pragma unroll
                for (int tt = 0; tt < 8; ++tt) {   // 8 x LDS.128 = 32 floats
                    const ulonglong2 w =
                        *reinterpret_cast<const ulonglong2*>(&s.W1T[k][c * 32 + 4 * tt]);
                    acc[2 * tt]     = ffma2(xk, w.x, acc[2 * tt]);
                    acc[2 * tt + 1] = ffma2(xk, w.y, acc[2 * tt + 1]);
                }
            }

            // consume the 16 output-pairs of this chunk into layer 2
            #pragma unroll
            for (int p = 0; p < 16; ++p) {
                float lo, hi; upk2(acc[p], lo, hi);
                const ull xa = pk2(silu_f(lo), silu_f(lo));
                const ull xb = pk2(silu_f(hi), silu_f(hi));
                const float* w2a = s.W2T[c * 32 + 2 * p];
                const float* w2b = s.W2T[c * 32 + 2 * p + 1];
                #pragma unroll
                for (int tt = 0; tt < 16; ++tt) {  // 2 x LDS.128 per tt pair-of-pairs
                    const ulonglong2 wa =
                        *reinterpret_cast<const ulonglong2*>(&w2a[4 * tt]);
                    const ulonglong2 wb =
                        *reinterpret_cast<const ulonglong2*>(&w2b[4 * tt]);
                    ull v0 = ffma2(xa, wa.x, a2[2 * tt]);
                    ull v1 = ffma2(xa, wa.y, a2[2 * tt + 1]);
                    a2[2 * tt]     = ffma2(xb, wb.x, v0);
                    a2[2 * tt + 1] = ffma2(xb, wb.y, v1);
                }
            }
        }

        // ---------------- layer 3 + epilogue (scalar) ----------------
        float u0 = s.b31[0], u1 = s.b31[1], sv = s.b32;
        #pragma unroll
        for (int t = 0; t < 16; ++t) {            // y[0..31]: u-branch
            float lo, hi; upk2(a2[t], lo, hi);
            const float y0 = silu_f(lo), y1 = silu_f(hi);
            u0 = fmaf(y0, s.W31[2 * t],      u0);
            u0 = fmaf(y1, s.W31[2 * t + 1],  u0);
            u1 = fmaf(y0, s.W31[32 + 2 * t],     u1);
            u1 = fmaf(y1, s.W31[32 + 2 * t + 1], u1);
        }
        #pragma unroll
        for (int t = 16; t < 32; ++t) {           // y[32..63]: alpha-branch
            float lo, hi; upk2(a2[t], lo, hi);
            sv = fmaf(silu_f(lo), s.W32[2 * (t - 16)],     sv);
            sv = fmaf(silu_f(hi), s.W32[2 * (t - 16) + 1], sv);
        }
        const float alpha = 4.0f * __fdividef(1.0f, 1.0f + __expf(-sv));

        const float rx = ov[6], ry = ov[7], vx = ov[8], vy = ov[9];
        const float barrier = fmaf(rx, rx, ry * ry) - 0.64f;          // R_SAFE^2
        const float lf  = -2.0f * fmaf(rx, vx, ry * vy);
        const float gx  = -2.0f * rx, gy = -2.0f * ry;
        const float h   = fmaf(alpha, barrier, lf);
        const float gg  = fmaf(gx, gx, gy * gy);
        const float viol = fmaf(gx, u0, gy * u1) - h;
        float lam = 0.0f;
        if (gg > 0.0f)
            lam = __fdividef(fmaxf(viol, 0.0f), fmaxf(gg, 1e-12f));

        out[r] = make_float2(fmaf(-lam, gx, u0), fmaf(-lam, gy, u1));
    }
}

extern "C" void kernel_launch(void* const* d_in, const int* in_sizes, int n_in,
                              void* d_out, int out_size)
{
    const float* obs = (const float*)d_in[0];
    const float* W1  = (const float*)d_in[1];
    const float* b1  = (const float*)d_in[2];
    const float* W21 = (const float*)d_in[3];
    const float* b21 = (const float*)d_in[4];
    const float* W22 = (const float*)d_in[5];
    const float* b22 = (const float*)d_in[6];
    const float* W31 = (const float*)d_in[7];
    const float* b31 = (const float*)d_in[8];
    const float* W32 = (const float*)d_in[9];
    const float* b32 = (const float*)d_in[10];
    float2* out = (float2*)d_out;

    const int n = in_sizes[0] / NF;
    const int rows_per_block = BLOCK * RPT;
    const int grid = (n + rows_per_block - 1) / rows_per_block;

    barriernet_kernel<<<grid, BLOCK>>>(obs, W1, b1, W21, b21, W22, b22,
                                       W31, b31, W32, b32, out, n);
}